// round 6
// baseline (speedup 1.0000x reference)
#include <cuda_runtime.h>
#include <mma.h>
#include <cstdint>

using namespace nvcuda;

// Problem dims (fixed by the dataset)
constexpr int BATCH = 16;
constexpr int T     = 2048;
constexpr int D     = 1024;   // K
constexpr int H     = 1024;   // H
constexpr int M     = BATCH * T;   // 32768
constexpr int N     = H;
constexpr int K     = D;

// Scratch for pre-activations (no runtime allocation allowed -> device globals)
__device__ float g_preZ[(size_t)M * N];
__device__ float g_preH[(size_t)M * N];

// ---------------------------------------------------------------------------
// Fused dual GEMM (TF32 wmma):  preZ = x * Wz^T,  preH = x * Wh^T
// x: (M,K) row-major;  Wz/Wh: (N,K) row-major (K-contiguous -> col-major B)
// Block tile 128x128, K-tile 32, cp.async double-buffered.
// 512 threads = 16 warps in 4x4; warp tile 32x32 = 2x2 wmma(16,16,8) frags
// per output matrix.
// ---------------------------------------------------------------------------
#define BM 128
#define BN 128
#define BK 32
#define SSTR (BK + 4)                 // padded row stride (floats); 144B rows
constexpr int TILE_FLOATS = BM * SSTR;        // one matrix, one stage
constexpr int STAGE_FLOATS = 3 * TILE_FLOATS; // A + Bz + Bh
constexpr size_t SMEM_BYTES = (size_t)2 * STAGE_FLOATS * sizeof(float);

__device__ __forceinline__ void cp_async16(void* smem_dst, const void* gmem_src) {
    uint32_t s;
    asm("{ .reg .u64 t; cvta.to.shared.u64 t, %1; cvt.u32.u64 %0, t; }"
        : "=r"(s) : "l"(smem_dst));
    asm volatile("cp.async.cg.shared.global [%0], [%1], 16;" :: "r"(s), "l"(gmem_src));
}
__device__ __forceinline__ void cp_async_commit() {
    asm volatile("cp.async.commit_group;" ::: "memory");
}
__device__ __forceinline__ void cp_async_wait0() {
    asm volatile("cp.async.wait_group 0;" ::: "memory");
}

__global__ __launch_bounds__(512, 1)
void dual_gemm_tf32(const float* __restrict__ x,
                    const float* __restrict__ Wz,
                    const float* __restrict__ Wh)
{
    extern __shared__ float smem[];
    // stage s: [sA | sZ | sH]
    float* sA[2] = { smem,                smem + STAGE_FLOATS };
    float* sZ[2] = { sA[0] + TILE_FLOATS, sA[1] + TILE_FLOATS };
    float* sH[2] = { sZ[0] + TILE_FLOATS, sZ[1] + TILE_FLOATS };

    const int tid    = threadIdx.x;
    const int warpId = tid >> 5;
    const int wr     = warpId >> 2;   // warp row 0..3 (M)
    const int wc     = warpId & 3;    // warp col 0..3 (N)

    const int m0 = blockIdx.y * BM;
    const int n0 = blockIdx.x * BN;

    wmma::fragment<wmma::accumulator, 16, 16, 8, float> accZ[2][2], accH[2][2];
    #pragma unroll
    for (int i = 0; i < 2; i++)
        #pragma unroll
        for (int j = 0; j < 2; j++) {
            wmma::fill_fragment(accZ[i][j], 0.0f);
            wmma::fill_fragment(accH[i][j], 0.0f);
        }

    // Global->shared mapping: per matrix, 128x32 floats = 1024 float4.
    // 512 threads -> 2 float4 each per matrix. f = tid + s*512:
    //   row = f >> 3, col4 = f & 7.
    const int r0 = tid >> 3;            // rows 0..63   (s=0)
    const int r1 = (tid + 512) >> 3;    // rows 64..127 (s=1)
    const int c4 = (tid & 7) * 4;       // float col 0,4,...,28

    const float* gA = x  + (size_t)m0 * K;
    const float* gZ = Wz + (size_t)n0 * K;
    const float* gH = Wh + (size_t)n0 * K;

    auto load_stage = [&](int st, int k0) {
        cp_async16(&sA[st][r0 * SSTR + c4], gA + (size_t)r0 * K + k0 + c4);
        cp_async16(&sA[st][r1 * SSTR + c4], gA + (size_t)r1 * K + k0 + c4);
        cp_async16(&sZ[st][r0 * SSTR + c4], gZ + (size_t)r0 * K + k0 + c4);
        cp_async16(&sZ[st][r1 * SSTR + c4], gZ + (size_t)r1 * K + k0 + c4);
        cp_async16(&sH[st][r0 * SSTR + c4], gH + (size_t)r0 * K + k0 + c4);
        cp_async16(&sH[st][r1 * SSTR + c4], gH + (size_t)r1 * K + k0 + c4);
        cp_async_commit();
    };

    load_stage(0, 0);

    constexpr int NK = K / BK;   // 32
    for (int kt = 0; kt < NK; kt++) {
        const int st = kt & 1;
        cp_async_wait0();
        __syncthreads();                       // stage st ready; prev compute done
        if (kt + 1 < NK) load_stage(st ^ 1, (kt + 1) * BK);

        #pragma unroll
        for (int ks = 0; ks < BK; ks += 8) {
            wmma::fragment<wmma::matrix_a, 16, 16, 8, wmma::precision::tf32, wmma::row_major> af[2];
            wmma::fragment<wmma::matrix_b, 16, 16, 8, wmma::precision::tf32, wmma::col_major> bzf[2], bhf[2];

            #pragma unroll
            for (int i = 0; i < 2; i++) {
                wmma::load_matrix_sync(af[i], &sA[st][(wr * 32 + i * 16) * SSTR + ks], SSTR);
                #pragma unroll
                for (int e = 0; e < af[i].num_elements; e++)
                    af[i].x[e] = wmma::__float_to_tf32(af[i].x[e]);
            }
            #pragma unroll
            for (int j = 0; j < 2; j++) {
                wmma::load_matrix_sync(bzf[j], &sZ[st][(wc * 32 + j * 16) * SSTR + ks], SSTR);
                wmma::load_matrix_sync(bhf[j], &sH[st][(wc * 32 + j * 16) * SSTR + ks], SSTR);
                #pragma unroll
                for (int e = 0; e < bzf[j].num_elements; e++) {
                    bzf[j].x[e] = wmma::__float_to_tf32(bzf[j].x[e]);
                    bhf[j].x[e] = wmma::__float_to_tf32(bhf[j].x[e]);
                }
            }
            #pragma unroll
            for (int i = 0; i < 2; i++)
                #pragma unroll
                for (int j = 0; j < 2; j++) {
                    wmma::mma_sync(accZ[i][j], af[i], bzf[j], accZ[i][j]);
                    wmma::mma_sync(accH[i][j], af[i], bhf[j], accH[i][j]);
                }
        }
        __syncthreads();                       // all reads of stage st done
    }

    // Epilogue: raw pre-activations to scratch (bias + sigmoid in scan)
    #pragma unroll
    for (int i = 0; i < 2; i++)
        #pragma unroll
        for (int j = 0; j < 2; j++) {
            const size_t off = (size_t)(m0 + wr * 32 + i * 16) * N + (n0 + wc * 32 + j * 16);
            wmma::store_matrix_sync(g_preZ + off, accZ[i][j], N, wmma::mem_row_major);
            wmma::store_matrix_sync(g_preH + off, accH[i][j], N, wmma::mem_row_major);
        }
}

// ---------------------------------------------------------------------------
// Sequential affine scan: one thread per (b, h) chain.
//   z    = sigmoid(preZ + b_z)
//   cand = preH + b_h
//   h    = h + z * (cand - h)
// U=16 batched loads -> 32 outstanding LDGs per thread for MLP.
// 128 threads x 128 blocks -> spreads across ~128 SMs.
// ---------------------------------------------------------------------------
constexpr int SCAN_U = 16;

__global__ __launch_bounds__(128)
void scan_kernel(const float* __restrict__ h_prev,
                 const float* __restrict__ b_z,
                 const float* __restrict__ b_h,
                 float* __restrict__ out)
{
    const int tid = blockIdx.x * blockDim.x + threadIdx.x;  // 0..16383
    const int b   = tid >> 10;       // / H
    const int hh  = tid & (H - 1);   // % H

    float h   = h_prev[tid];
    const float vbz = b_z[hh];
    const float vbh = b_h[hh];

    const size_t base = (size_t)b * T * H + hh;
    const float* pz = g_preZ + base;
    const float* ph = g_preH + base;
    float*       po = out   + base;

    for (int t = 0; t < T; t += SCAN_U) {
        float zb[SCAN_U], cb[SCAN_U];
        #pragma unroll
        for (int u = 0; u < SCAN_U; u++) {
            zb[u] = __ldg(pz + (size_t)(t + u) * H);
            cb[u] = __ldg(ph + (size_t)(t + u) * H);
        }
        #pragma unroll
        for (int u = 0; u < SCAN_U; u++) {
            const float z    = 1.0f / (1.0f + __expf(-(zb[u] + vbz)));
            const float cand = cb[u] + vbh;
            h = fmaf(z, cand - h, h);
            po[(size_t)(t + u) * H] = h;
        }
    }
}

// ---------------------------------------------------------------------------
// Harness entry. Inputs (metadata order): x, h_prev, W_z, b_z, W_h, b_h
// Output: (B, T, H) float32
// ---------------------------------------------------------------------------
extern "C" void kernel_launch(void* const* d_in, const int* in_sizes, int n_in,
                              void* d_out, int out_size)
{
    const float* x      = (const float*)d_in[0];
    const float* h_prev = (const float*)d_in[1];
    const float* Wz     = (const float*)d_in[2];
    const float* bz     = (const float*)d_in[3];
    const float* Wh     = (const float*)d_in[4];
    const float* bh     = (const float*)d_in[5];
    float* out = (float*)d_out;

    // Unconditional + idempotent (no static guards allowed; not a stream op,
    // legal during graph capture).
    cudaFuncSetAttribute(dual_gemm_tf32,
                         cudaFuncAttributeMaxDynamicSharedMemorySize,
                         (int)SMEM_BYTES);

    dim3 gemm_grid(N / BN, M / BM);   // (8, 256): n-fastest -> A-tile reuse in L2
    dual_gemm_tf32<<<gemm_grid, 512, SMEM_BYTES>>>(x, Wz, Wh);

    const int chains = BATCH * H;     // 16384
    scan_kernel<<<chains / 128, 128>>>(h_prev, bz, bh, out);
}

// round 15
// speedup vs baseline: 2.6997x; 2.6997x over previous
#include <cuda_runtime.h>
#include <cuda_fp16.h>
#include <mma.h>
#include <cstdint>

using namespace nvcuda;

// ---------------------------------------------------------------------------
// Problem dims (fixed by the dataset)
// ---------------------------------------------------------------------------
constexpr int BATCH = 16;
constexpr int T     = 2048;
constexpr int D     = 1024;        // K
constexpr int HDIM  = 1024;        // H
constexpr int M     = BATCH * T;   // 32768
constexpr int N     = HDIM;        // 1024
constexpr int K     = D;           // 1024

// ---------------------------------------------------------------------------
// Device-global scratch (no runtime allocation allowed)
// ---------------------------------------------------------------------------
__device__ __align__(256) float  g_preZ[(size_t)M * N];
__device__ __align__(256) float  g_preH[(size_t)M * N];
__device__ __align__(256) __half g_xh [(size_t)M * K];   // 64 MB fp16 x
__device__ __align__(256) __half g_wzh[(size_t)N * K];   // 2 MB fp16 Wz
__device__ __align__(256) __half g_whh[(size_t)N * K];   // 2 MB fp16 Wh

// ---------------------------------------------------------------------------
// cp.async helpers
// ---------------------------------------------------------------------------
__device__ __forceinline__ void cp_async16(void* smem_dst, const void* gmem_src) {
    uint32_t s;
    asm("{ .reg .u64 t; cvta.to.shared.u64 t, %1; cvt.u32.u64 %0, t; }"
        : "=r"(s) : "l"(smem_dst));
    asm volatile("cp.async.cg.shared.global [%0], [%1], 16;" :: "r"(s), "l"(gmem_src));
}
#define CP_COMMIT() asm volatile("cp.async.commit_group;" ::: "memory")
#define CP_WAIT0()  asm volatile("cp.async.wait_group 0;" ::: "memory")

// ---------------------------------------------------------------------------
// Pass 0: convert f32 -> fp16 (RN). fp16 has the same 11-bit significand as
// tf32, so GEMM numerics match the measured tf32 path (rel_err 3.6e-4).
// Each thread: one float4 -> 4 halfs (8 B store).
// ---------------------------------------------------------------------------
__global__ void to_half_kernel(const float4* __restrict__ src,
                               __half2* __restrict__ dst) {
    const size_t i = (size_t)blockIdx.x * blockDim.x + threadIdx.x;
    const float4 v = src[i];
    dst[2 * i + 0] = __floats2half2_rn(v.x, v.y);
    dst[2 * i + 1] = __floats2half2_rn(v.z, v.w);
}

// ---------------------------------------------------------------------------
// Pass 1: fused dual GEMM (fp16 wmma, fp32 accum):
//   preZ = x * Wz^T , preH = x * Wh^T
// x: (M,K) row-major; Wz/Wh: (N,K) row-major (K-contig -> col_major B frags).
// Block tile 128x128, BK=64, cp.async double-buffered.
// 512 threads = 16 warps (4x4); warp tile 32x32 = 2x2 wmma(16,16,16) frags
// per output matrix.
// ---------------------------------------------------------------------------
#define BM 128
#define BN 128
#define BK 64
#define SSTR 72                        // padded row stride in halfs (144 B, mult of 8)
constexpr int TILE_H   = BM * SSTR;             // halfs per matrix per stage
constexpr int STAGE_H  = 3 * TILE_H;            // A + Bz + Bh
constexpr size_t SMEM_BYTES = (size_t)2 * STAGE_H * sizeof(__half);  // 110592 B

__global__ __launch_bounds__(512, 1)
void dual_gemm_fp16(const __half* __restrict__ xh,
                    const __half* __restrict__ wzh,
                    const __half* __restrict__ whh)
{
    extern __shared__ __half smem[];
    __half* sA[2] = { smem,                smem + STAGE_H };
    __half* sZ[2] = { sA[0] + TILE_H,      sA[1] + TILE_H };
    __half* sH[2] = { sZ[0] + TILE_H,      sZ[1] + TILE_H };

    const int tid    = threadIdx.x;
    const int warpId = tid >> 5;
    const int wr     = warpId >> 2;    // warp row 0..3 (M)
    const int wc     = warpId & 3;     // warp col 0..3 (N)

    const int m0 = blockIdx.y * BM;
    const int n0 = blockIdx.x * BN;

    wmma::fragment<wmma::accumulator, 16, 16, 16, float> accZ[2][2], accH[2][2];
    #pragma unroll
    for (int i = 0; i < 2; i++)
        #pragma unroll
        for (int j = 0; j < 2; j++) {
            wmma::fill_fragment(accZ[i][j], 0.0f);
            wmma::fill_fragment(accH[i][j], 0.0f);
        }

    // Global->shared mapping: per matrix, 128 rows x 64 halfs = 1024 x 16B.
    // 512 threads -> 2 chunks each per matrix. f = tid + s*512:
    //   row = f >> 3 (8 chunks/row), col8 = (f & 7)*8 halfs.
    const int r0 = tid >> 3;             // rows 0..63   (s=0)
    const int r1 = (tid + 512) >> 3;     // rows 64..127 (s=1)
    const int c8 = (tid & 7) * 8;        // half col 0,8,...,56

    const __half* gA = xh  + (size_t)m0 * K;
    const __half* gZ = wzh + (size_t)n0 * K;
    const __half* gH = whh + (size_t)n0 * K;

    auto load_stage = [&](int st, int k0) {
        cp_async16(&sA[st][r0 * SSTR + c8], gA + (size_t)r0 * K + k0 + c8);
        cp_async16(&sA[st][r1 * SSTR + c8], gA + (size_t)r1 * K + k0 + c8);
        cp_async16(&sZ[st][r0 * SSTR + c8], gZ + (size_t)r0 * K + k0 + c8);
        cp_async16(&sZ[st][r1 * SSTR + c8], gZ + (size_t)r1 * K + k0 + c8);
        cp_async16(&sH[st][r0 * SSTR + c8], gH + (size_t)r0 * K + k0 + c8);
        cp_async16(&sH[st][r1 * SSTR + c8], gH + (size_t)r1 * K + k0 + c8);
        CP_COMMIT();
    };

    load_stage(0, 0);

    constexpr int NK = K / BK;   // 16
    for (int kt = 0; kt < NK; kt++) {
        const int st = kt & 1;
        CP_WAIT0();
        __syncthreads();                       // stage st ready; prev compute done
        if (kt + 1 < NK) load_stage(st ^ 1, (kt + 1) * BK);

        #pragma unroll
        for (int ks = 0; ks < BK; ks += 16) {
            wmma::fragment<wmma::matrix_a, 16, 16, 16, __half, wmma::row_major> af[2];
            #pragma unroll
            for (int i = 0; i < 2; i++)
                wmma::load_matrix_sync(af[i], &sA[st][(wr * 32 + i * 16) * SSTR + ks], SSTR);

            {   // Z-matrix B frags, scoped to limit register liveness
                wmma::fragment<wmma::matrix_b, 16, 16, 16, __half, wmma::col_major> bzf[2];
                #pragma unroll
                for (int j = 0; j < 2; j++)
                    wmma::load_matrix_sync(bzf[j], &sZ[st][(wc * 32 + j * 16) * SSTR + ks], SSTR);
                #pragma unroll
                for (int i = 0; i < 2; i++)
                    #pragma unroll
                    for (int j = 0; j < 2; j++)
                        wmma::mma_sync(accZ[i][j], af[i], bzf[j], accZ[i][j]);
            }
            {   // H-matrix B frags
                wmma::fragment<wmma::matrix_b, 16, 16, 16, __half, wmma::col_major> bhf[2];
                #pragma unroll
                for (int j = 0; j < 2; j++)
                    wmma::load_matrix_sync(bhf[j], &sH[st][(wc * 32 + j * 16) * SSTR + ks], SSTR);
                #pragma unroll
                for (int i = 0; i < 2; i++)
                    #pragma unroll
                    for (int j = 0; j < 2; j++)
                        wmma::mma_sync(accH[i][j], af[i], bhf[j], accH[i][j]);
            }
        }
        __syncthreads();                       // all reads of stage st done
    }

    // Epilogue: raw pre-activations to scratch (bias + sigmoid in scan)
    #pragma unroll
    for (int i = 0; i < 2; i++)
        #pragma unroll
        for (int j = 0; j < 2; j++) {
            const size_t off = (size_t)(m0 + wr * 32 + i * 16) * N + (n0 + wc * 32 + j * 16);
            wmma::store_matrix_sync(g_preZ + off, accZ[i][j], N, wmma::mem_row_major);
            wmma::store_matrix_sync(g_preH + off, accH[i][j], N, wmma::mem_row_major);
        }
}

// ---------------------------------------------------------------------------
// Pass 2: sequential affine scan (unchanged; 222 us measured).
//   z = sigmoid(preZ + b_z); cand = preH + b_h; h = h + z*(cand - h)
// ---------------------------------------------------------------------------
constexpr int SCAN_U = 16;

__global__ __launch_bounds__(128)
void scan_kernel(const float* __restrict__ h_prev,
                 const float* __restrict__ b_z,
                 const float* __restrict__ b_h,
                 float* __restrict__ out)
{
    const int tid = blockIdx.x * blockDim.x + threadIdx.x;  // 0..16383
    const int b   = tid >> 10;
    const int hh  = tid & (HDIM - 1);

    float h = h_prev[tid];
    const float vbz = b_z[hh];
    const float vbh = b_h[hh];

    const size_t base = (size_t)b * T * HDIM + hh;
    const float* pz = g_preZ + base;
    const float* ph = g_preH + base;
    float*       po = out   + base;

    for (int t = 0; t < T; t += SCAN_U) {
        float zb[SCAN_U], cb[SCAN_U];
        #pragma unroll
        for (int u = 0; u < SCAN_U; u++) {
            zb[u] = __ldg(pz + (size_t)(t + u) * HDIM);
            cb[u] = __ldg(ph + (size_t)(t + u) * HDIM);
        }
        #pragma unroll
        for (int u = 0; u < SCAN_U; u++) {
            const float z    = 1.0f / (1.0f + __expf(-(zb[u] + vbz)));
            const float cand = cb[u] + vbh;
            h = fmaf(z, cand - h, h);
            po[(size_t)(t + u) * HDIM] = h;
        }
    }
}

// ---------------------------------------------------------------------------
// Harness entry. Inputs (metadata order): x, h_prev, W_z, b_z, W_h, b_h
// ---------------------------------------------------------------------------
extern "C" void kernel_launch(void* const* d_in, const int* in_sizes, int n_in,
                              void* d_out, int out_size)
{
    const float* x      = (const float*)d_in[0];
    const float* h_prev = (const float*)d_in[1];
    const float* Wz     = (const float*)d_in[2];
    const float* bz     = (const float*)d_in[3];
    const float* Wh     = (const float*)d_in[4];
    const float* bh     = (const float*)d_in[5];
    float* out = (float*)d_out;

    cudaFuncSetAttribute(dual_gemm_fp16,
                         cudaFuncAttributeMaxDynamicSharedMemorySize,
                         (int)SMEM_BYTES);

    void *p_xh, *p_wzh, *p_whh;
    cudaGetSymbolAddress(&p_xh,  g_xh);
    cudaGetSymbolAddress(&p_wzh, g_wzh);
    cudaGetSymbolAddress(&p_whh, g_whh);

    // f32 -> fp16 conversion (4 elems/thread)
    to_half_kernel<<<((size_t)M * K / 4) / 256, 256>>>((const float4*)x,  (__half2*)p_xh);
    to_half_kernel<<<((size_t)N * K / 4) / 256, 256>>>((const float4*)Wz, (__half2*)p_wzh);
    to_half_kernel<<<((size_t)N * K / 4) / 256, 256>>>((const float4*)Wh, (__half2*)p_whh);

    dim3 gemm_grid(N / BN, M / BM);   // (8, 256): n-fastest -> x-tile reuse in L2
    dual_gemm_fp16<<<gemm_grid, 512, SMEM_BYTES>>>((const __half*)p_xh,
                                                   (const __half*)p_wzh,
                                                   (const __half*)p_whh);

    const int chains = BATCH * HDIM;  // 16384
    scan_kernel<<<chains / 128, 128>>>(h_prev, bz, bh, out);
}